// round 2
// baseline (speedup 1.0000x reference)
#include <cuda_runtime.h>
#include <math.h>

// Problem constants
#define BB 4
#define CC 3
#define HH 32
#define WW 32
#define NIMG 32
#define PP (NIMG*HH*WW)      // 32768 dataset patches
#define QQ (BB*HH*WW)        // 4096 queries
#define KD 27                // patch feature dim (C*9)
#define KP 28                // padded row: 27 features + bias
#define NCHUNK 32            // patch chunks
#define CHUNK (PP/NCHUNK)    // 1024 patches per chunk
#define QPB 256              // queries per block (1 per thread)
#define QTILES (QQ/QPB)      // 16
#define PSTAGE 128           // patches staged in smem per step

// Scratch (static device globals: no allocation allowed)
__device__ float g_pbuf[PP*KP];               // [P][28]: 27 patch vals + logit bias
__device__ float g_qbuf[QQ*KP];               // [Q][28]: 27 scaled query vals
__device__ float g_partial[QQ*NCHUNK*8];      // per (q,chunk): m, sumw, wc0, wc1, wc2

// ---------------------------------------------------------------------------
// Prep: build scaled query patches (wrap pad) and dataset patches (zero pad)
// with the -mu^2/(2 sigma^2) * ||k||^2 bias baked in.
// ---------------------------------------------------------------------------
__global__ void prep_kernel(const float* __restrict__ x,
                            const float* __restrict__ images,
                            const float* __restrict__ mu_sched,
                            const float* __restrict__ sigma_sched,
                            const int* __restrict__ tptr)
{
    const int t = *tptr;
    const float mu = mu_sched[t];
    const float sg = sigma_sched[t];
    const float inv2s2 = 1.0f / (2.0f * sg * sg);
    const float a  = 2.0f * mu * inv2s2;     // folded into query
    const float nb = -mu * mu * inv2s2;      // bias scale on ||k||^2

    int gid = blockIdx.x * blockDim.x + threadIdx.x;
    if (gid < PP) {
        // dataset patch p = (n, i, j), zero padding
        int p = gid;
        int n = p >> 10;
        int i = (p >> 5) & 31;
        int j = p & 31;
        float pn = 0.0f;
        #pragma unroll
        for (int c = 0; c < CC; c++) {
            #pragma unroll
            for (int di = 0; di < 3; di++) {
                #pragma unroll
                for (int dj = 0; dj < 3; dj++) {
                    int ii = i + di - 1;
                    int jj = j + dj - 1;
                    float v = 0.0f;
                    if (ii >= 0 && ii < HH && jj >= 0 && jj < WW)
                        v = images[(((n*CC + c) << 5) + ii) * WW + jj];
                    g_pbuf[p*KP + c*9 + di*3 + dj] = v;
                    pn += v * v;
                }
            }
        }
        g_pbuf[p*KP + 27] = nb * pn;
    } else if (gid < PP + QQ) {
        // query q = (b, h, w), circular (wrap) padding, scaled by a
        int q = gid - PP;
        int b = q >> 10;
        int h = (q >> 5) & 31;
        int w = q & 31;
        #pragma unroll
        for (int c = 0; c < CC; c++) {
            #pragma unroll
            for (int di = 0; di < 3; di++) {
                #pragma unroll
                for (int dj = 0; dj < 3; dj++) {
                    int ii = (h + di - 1) & 31;   // wrap (H=32 power of two)
                    int jj = (w + dj - 1) & 31;
                    g_qbuf[q*KP + c*9 + di*3 + dj] =
                        a * x[(((b*CC + c) << 5) + ii) * WW + jj];
                }
            }
        }
        g_qbuf[q*KP + 27] = 0.0f;
    }
}

// ---------------------------------------------------------------------------
// Main: each thread = 1 query; block of 256 queries streams a 1024-patch chunk
// through smem; online softmax over logits s = q'.k + bias_k.
// ---------------------------------------------------------------------------
__global__ void __launch_bounds__(QPB)
score_main_kernel()
{
    __shared__ float sp[PSTAGE * KP];

    const int tid = threadIdx.x;
    const int q   = blockIdx.x * QPB + tid;

    float qr[KD];
    {
        const float* qp = g_qbuf + q * KP;
        #pragma unroll
        for (int k = 0; k < KD; k++) qr[k] = qp[k];
    }

    float m = -1e30f, sw = 0.0f, w0 = 0.0f, w1 = 0.0f, w2 = 0.0f;

    const int pbase = blockIdx.y * CHUNK;

    for (int s0 = 0; s0 < CHUNK; s0 += PSTAGE) {
        __syncthreads();
        {
            const float* src = g_pbuf + (size_t)(pbase + s0) * KP;
            #pragma unroll
            for (int i = tid; i < PSTAGE * KP; i += QPB) sp[i] = src[i];
        }
        __syncthreads();

        for (int j = 0; j < PSTAGE; j++) {
            const float4* pv = (const float4*)(sp + j * KP);
            float4 v0 = pv[0], v1 = pv[1], v2 = pv[2], v3 = pv[3];
            float4 v4 = pv[4], v5 = pv[5], v6 = pv[6];

            float s = v6.w;                  // bias = -mu^2/(2s^2) * ||k||^2
            s += qr[ 0]*v0.x; s += qr[ 1]*v0.y; s += qr[ 2]*v0.z; s += qr[ 3]*v0.w;
            s += qr[ 4]*v1.x; s += qr[ 5]*v1.y; s += qr[ 6]*v1.z; s += qr[ 7]*v1.w;
            s += qr[ 8]*v2.x; s += qr[ 9]*v2.y; s += qr[10]*v2.z; s += qr[11]*v2.w;
            s += qr[12]*v3.x; s += qr[13]*v3.y; s += qr[14]*v3.z; s += qr[15]*v3.w;
            s += qr[16]*v4.x; s += qr[17]*v4.y; s += qr[18]*v4.z; s += qr[19]*v4.w;
            s += qr[20]*v5.x; s += qr[21]*v5.y; s += qr[22]*v5.z; s += qr[23]*v5.w;
            s += qr[24]*v6.x; s += qr[25]*v6.y; s += qr[26]*v6.z;

            if (s > m) {                     // rare after warmup
                float corr = __expf(m - s);
                sw *= corr; w0 *= corr; w1 *= corr; w2 *= corr;
                m = s;
            }
            float w = __expf(s - m);
            sw += w;
            w0 += w * v1.x;   // pcenter c=0 -> feature 4
            w1 += w * v3.y;   // pcenter c=1 -> feature 13
            w2 += w * v5.z;   // pcenter c=2 -> feature 22
        }
    }

    float* o = g_partial + ((size_t)q * NCHUNK + blockIdx.y) * 8;
    o[0] = m; o[1] = sw; o[2] = w0; o[3] = w1; o[4] = w2;
}

// ---------------------------------------------------------------------------
// Finalize: merge chunk partials (max-rescale), form output.
// out = -(x - mu * wc/sum_w) / sigma^2
// ---------------------------------------------------------------------------
__global__ void finalize_kernel(const float* __restrict__ x,
                                const float* __restrict__ mu_sched,
                                const float* __restrict__ sigma_sched,
                                const int* __restrict__ tptr,
                                float* __restrict__ out)
{
    int q = blockIdx.x * blockDim.x + threadIdx.x;
    if (q >= QQ) return;

    const int t = *tptr;
    const float mu = mu_sched[t];
    const float sg = sigma_sched[t];
    const float is2 = 1.0f / (sg * sg);

    const float* pr = g_partial + (size_t)q * NCHUNK * 8;

    float M = -1e30f;
    #pragma unroll
    for (int i = 0; i < NCHUNK; i++) M = fmaxf(M, pr[i*8]);

    float S = 0.0f, c0 = 0.0f, c1 = 0.0f, c2 = 0.0f;
    #pragma unroll
    for (int i = 0; i < NCHUNK; i++) {
        float corr = __expf(pr[i*8] - M);
        S  += pr[i*8 + 1] * corr;
        c0 += pr[i*8 + 2] * corr;
        c1 += pr[i*8 + 3] * corr;
        c2 += pr[i*8 + 4] * corr;
    }
    float inv = 1.0f / S;

    int b = q >> 10;
    int h = (q >> 5) & 31;
    int w = q & 31;
    int pix = (h << 5) + w;

    out[((b*CC + 0) << 10) + pix] = -(x[((b*CC + 0) << 10) + pix] - mu * c0 * inv) * is2;
    out[((b*CC + 1) << 10) + pix] = -(x[((b*CC + 1) << 10) + pix] - mu * c1 * inv) * is2;
    out[((b*CC + 2) << 10) + pix] = -(x[((b*CC + 2) << 10) + pix] - mu * c2 * inv) * is2;
}

// ---------------------------------------------------------------------------
extern "C" void kernel_launch(void* const* d_in, const int* in_sizes, int n_in,
                              void* d_out, int out_size)
{
    const float* x      = (const float*)d_in[0];
    const float* images = (const float*)d_in[1];
    const float* mu_s   = (const float*)d_in[2];
    const float* sg_s   = (const float*)d_in[3];
    const int*   tptr   = (const int*)d_in[4];
    float* out = (float*)d_out;

    prep_kernel<<<(PP + QQ + 255) / 256, 256>>>(x, images, mu_s, sg_s, tptr);
    score_main_kernel<<<dim3(QTILES, NCHUNK), QPB>>>();
    finalize_kernel<<<(QQ + 255) / 256, 256>>>(x, mu_s, sg_s, tptr, out);
}

// round 3
// speedup vs baseline: 1.2288x; 1.2288x over previous
#include <cuda_runtime.h>
#include <math.h>

// Problem constants
#define BB 4
#define CC 3
#define HH 32
#define WW 32
#define NIMG 32
#define PP (NIMG*HH*WW)      // 32768 dataset patches
#define QQ (BB*HH*WW)        // 4096 queries
#define KD 27                // patch feature dim (C*9)
#define KP 28                // padded slots: 27 features + bias
#define NCHUNK 74            // patch chunks: 16*74 = 1184 = 148*8 blocks (perfect waves)
#define CHUNK 444            // ceil-ish chunk (74*444 >= 32768), even
#define QPB 256              // queries per block (1 per thread)
#define QTILES (QQ/QPB)      // 16
#define PSTAGE 128           // patches staged in smem per step (64 pairs)

typedef unsigned long long u64;

// Scratch (static device globals: no allocation allowed)
// g_pbuf layout: [P/2 pairs][28 k][2 lanes] -> pair-interleaved for f32x2
__device__ float g_pbuf[PP*KP];
__device__ float g_qbuf[QQ*KP];               // [Q][28]: scaled query (log2 domain)
__device__ float g_partial[QQ*NCHUNK*8];      // per (q,chunk): m, sumw, wc0, wc1, wc2

// ---- packed f32x2 helpers -------------------------------------------------
__device__ __forceinline__ u64 pk2(float lo, float hi) {
    u64 r; asm("mov.b64 %0,{%1,%2};" : "=l"(r) : "f"(lo), "f"(hi)); return r;
}
__device__ __forceinline__ void up2(u64 v, float& lo, float& hi) {
    asm("mov.b64 {%0,%1},%2;" : "=f"(lo), "=f"(hi) : "l"(v));
}
__device__ __forceinline__ u64 ffma2(u64 a, u64 b, u64 c) {
    u64 d; asm("fma.rn.f32x2 %0,%1,%2,%3;" : "=l"(d) : "l"(a), "l"(b), "l"(c)); return d;
}
__device__ __forceinline__ u64 fadd2(u64 a, u64 b) {
    u64 d; asm("add.rn.f32x2 %0,%1,%2;" : "=l"(d) : "l"(a), "l"(b)); return d;
}
__device__ __forceinline__ u64 fmul2(u64 a, u64 b) {
    u64 d; asm("mul.rn.f32x2 %0,%1,%2;" : "=l"(d) : "l"(a), "l"(b)); return d;
}
__device__ __forceinline__ float ex2f(float x) {
    float r; asm("ex2.approx.f32 %0,%1;" : "=f"(r) : "f"(x)); return r;
}

// ---------------------------------------------------------------------------
// Prep: dataset patches (zero pad) in pair-interleaved layout with log2-domain
// bias; queries (wrap pad) scaled by 2*mu/(2 sigma^2) * log2(e).
// ---------------------------------------------------------------------------
__global__ void prep_kernel(const float* __restrict__ x,
                            const float* __restrict__ images,
                            const float* __restrict__ mu_sched,
                            const float* __restrict__ sigma_sched,
                            const int* __restrict__ tptr)
{
    const int t = *tptr;
    const float mu = mu_sched[t];
    const float sg = sigma_sched[t];
    const float LOG2E = 1.4426950408889634f;
    const float inv2s2 = 1.0f / (2.0f * sg * sg);
    const float a  = 2.0f * mu * inv2s2 * LOG2E;   // folded into query
    const float nb = -mu * mu * inv2s2 * LOG2E;    // bias scale on ||k||^2

    int gid = blockIdx.x * blockDim.x + threadIdx.x;
    if (gid < PP) {
        int p = gid;
        int n = p >> 10;
        int i = (p >> 5) & 31;
        int j = p & 31;
        int pr  = p >> 1;       // pair index
        int ln  = p & 1;        // lane within pair
        float pn = 0.0f;
        #pragma unroll
        for (int c = 0; c < CC; c++) {
            #pragma unroll
            for (int di = 0; di < 3; di++) {
                #pragma unroll
                for (int dj = 0; dj < 3; dj++) {
                    int ii = i + di - 1;
                    int jj = j + dj - 1;
                    float v = 0.0f;
                    if (ii >= 0 && ii < HH && jj >= 0 && jj < WW)
                        v = images[(((n*CC + c) << 5) + ii) * WW + jj];
                    g_pbuf[((pr*KP) + c*9 + di*3 + dj)*2 + ln] = v;
                    pn += v * v;
                }
            }
        }
        g_pbuf[((pr*KP) + 27)*2 + ln] = nb * pn;
    } else if (gid < PP + QQ) {
        int q = gid - PP;
        int b = q >> 10;
        int h = (q >> 5) & 31;
        int w = q & 31;
        #pragma unroll
        for (int c = 0; c < CC; c++) {
            #pragma unroll
            for (int di = 0; di < 3; di++) {
                #pragma unroll
                for (int dj = 0; dj < 3; dj++) {
                    int ii = (h + di - 1) & 31;   // wrap
                    int jj = (w + dj - 1) & 31;
                    g_qbuf[q*KP + c*9 + di*3 + dj] =
                        a * x[(((b*CC + c) << 5) + ii) * WW + jj];
                }
            }
        }
        g_qbuf[q*KP + 27] = 0.0f;
    }
}

// ---------------------------------------------------------------------------
// Main: each thread = 1 query; processes patch PAIRS with packed f32x2 FMA.
// Online softmax in log2 domain.
// ---------------------------------------------------------------------------
__global__ void __launch_bounds__(QPB)
score_main_kernel()
{
    __shared__ __align__(16) float sp[PSTAGE * KP];   // 64 pairs * 56 floats

    const int tid = threadIdx.x;
    const int q   = blockIdx.x * QPB + tid;

    u64 q2[KD];
    {
        const float* qp = g_qbuf + q * KP;
        #pragma unroll
        for (int k = 0; k < KD; k++) { float v = qp[k]; q2[k] = pk2(v, v); }
    }

    const u64 ZERO2 = 0ULL;
    float m = -1e30f;
    u64 sw2 = ZERO2, w02 = ZERO2, w12 = ZERO2, w22 = ZERO2;

    const int pbase = blockIdx.y * CHUNK;
    const int pend  = (pbase + CHUNK < PP) ? (pbase + CHUNK) : PP;

    for (int s0 = pbase; s0 < pend; s0 += PSTAGE) {
        const int cnt   = (pend - s0 < PSTAGE) ? (pend - s0) : PSTAGE;  // even
        const int npair = cnt >> 1;
        __syncthreads();
        {
            const float4* src = (const float4*)(g_pbuf + (size_t)(s0 >> 1) * KP * 2);
            float4* dst = (float4*)sp;
            const int nv = npair * 14;          // 14 float4 per pair
            for (int i = tid; i < nv; i += QPB) dst[i] = src[i];
        }
        __syncthreads();

        for (int jp = 0; jp < npair; jp++) {
            const ulonglong2* dv = (const ulonglong2*)(sp + jp * (KP*2));
            ulonglong2 e0 = dv[0], e1 = dv[1], e2 = dv[2],  e3 = dv[3];
            ulonglong2 e4 = dv[4], e5 = dv[5], e6 = dv[6],  e7 = dv[7];
            ulonglong2 e8 = dv[8], e9 = dv[9], e10 = dv[10], e11 = dv[11];
            ulonglong2 e12 = dv[12], e13 = dv[13];

            // dot over 27 features + bias (e13.y), 4 independent chains
            u64 a0 = e13.y, a1 = ZERO2, a2 = ZERO2, a3 = ZERO2;
            a0 = ffma2(q2[ 0], e0.x,  a0);  a1 = ffma2(q2[ 1], e0.y,  a1);
            a2 = ffma2(q2[ 2], e1.x,  a2);  a3 = ffma2(q2[ 3], e1.y,  a3);
            a0 = ffma2(q2[ 4], e2.x,  a0);  a1 = ffma2(q2[ 5], e2.y,  a1);
            a2 = ffma2(q2[ 6], e3.x,  a2);  a3 = ffma2(q2[ 7], e3.y,  a3);
            a0 = ffma2(q2[ 8], e4.x,  a0);  a1 = ffma2(q2[ 9], e4.y,  a1);
            a2 = ffma2(q2[10], e5.x,  a2);  a3 = ffma2(q2[11], e5.y,  a3);
            a0 = ffma2(q2[12], e6.x,  a0);  a1 = ffma2(q2[13], e6.y,  a1);
            a2 = ffma2(q2[14], e7.x,  a2);  a3 = ffma2(q2[15], e7.y,  a3);
            a0 = ffma2(q2[16], e8.x,  a0);  a1 = ffma2(q2[17], e8.y,  a1);
            a2 = ffma2(q2[18], e9.x,  a2);  a3 = ffma2(q2[19], e9.y,  a3);
            a0 = ffma2(q2[20], e10.x, a0);  a1 = ffma2(q2[21], e10.y, a1);
            a2 = ffma2(q2[22], e11.x, a2);  a3 = ffma2(q2[23], e11.y, a3);
            a0 = ffma2(q2[24], e12.x, a0);  a1 = ffma2(q2[25], e12.y, a1);
            a2 = ffma2(q2[26], e13.x, a2);
            u64 s2 = fadd2(fadd2(a0, a1), fadd2(a2, a3));

            float slo, shi; up2(s2, slo, shi);
            float mx = fmaxf(slo, shi);
            if (mx > m) {                       // rare after warmup
                float corr = ex2f(m - mx);
                u64 c2 = pk2(corr, corr);
                sw2 = fmul2(sw2, c2); w02 = fmul2(w02, c2);
                w12 = fmul2(w12, c2); w22 = fmul2(w22, c2);
                m = mx;
            }
            u64 w2 = pk2(ex2f(slo - m), ex2f(shi - m));
            sw2 = fadd2(sw2, w2);
            w02 = ffma2(w2, e2.x,  w02);   // pcenter c=0 -> k=4
            w12 = ffma2(w2, e6.y,  w12);   // pcenter c=1 -> k=13
            w22 = ffma2(w2, e11.x, w22);   // pcenter c=2 -> k=22
        }
    }

    float sa, sb, c0a, c0b, c1a, c1b, c2a, c2b;
    up2(sw2, sa, sb); up2(w02, c0a, c0b); up2(w12, c1a, c1b); up2(w22, c2a, c2b);

    float* o = g_partial + ((size_t)q * NCHUNK + blockIdx.y) * 8;
    o[0] = m; o[1] = sa + sb; o[2] = c0a + c0b; o[3] = c1a + c1b; o[4] = c2a + c2b;
}

// ---------------------------------------------------------------------------
// Finalize: merge chunk partials (log2-domain max-rescale), form output.
// ---------------------------------------------------------------------------
__global__ void finalize_kernel(const float* __restrict__ x,
                                const float* __restrict__ mu_sched,
                                const float* __restrict__ sigma_sched,
                                const int* __restrict__ tptr,
                                float* __restrict__ out)
{
    int q = blockIdx.x * blockDim.x + threadIdx.x;
    if (q >= QQ) return;

    const int t = *tptr;
    const float mu = mu_sched[t];
    const float sg = sigma_sched[t];
    const float is2 = 1.0f / (sg * sg);

    const float* pr = g_partial + (size_t)q * NCHUNK * 8;

    float M = -1e30f;
    #pragma unroll
    for (int i = 0; i < NCHUNK; i++) M = fmaxf(M, pr[i*8]);

    float S = 0.0f, c0 = 0.0f, c1 = 0.0f, c2 = 0.0f;
    #pragma unroll
    for (int i = 0; i < NCHUNK; i++) {
        float corr = ex2f(pr[i*8] - M);
        S  += pr[i*8 + 1] * corr;
        c0 += pr[i*8 + 2] * corr;
        c1 += pr[i*8 + 3] * corr;
        c2 += pr[i*8 + 4] * corr;
    }
    float inv = 1.0f / S;

    int b = q >> 10;
    int h = (q >> 5) & 31;
    int w = q & 31;
    int pix = (h << 5) + w;

    out[((b*CC + 0) << 10) + pix] = -(x[((b*CC + 0) << 10) + pix] - mu * c0 * inv) * is2;
    out[((b*CC + 1) << 10) + pix] = -(x[((b*CC + 1) << 10) + pix] - mu * c1 * inv) * is2;
    out[((b*CC + 2) << 10) + pix] = -(x[((b*CC + 2) << 10) + pix] - mu * c2 * inv) * is2;
}

// ---------------------------------------------------------------------------
extern "C" void kernel_launch(void* const* d_in, const int* in_sizes, int n_in,
                              void* d_out, int out_size)
{
    const float* x      = (const float*)d_in[0];
    const float* images = (const float*)d_in[1];
    const float* mu_s   = (const float*)d_in[2];
    const float* sg_s   = (const float*)d_in[3];
    const int*   tptr   = (const int*)d_in[4];
    float* out = (float*)d_out;

    prep_kernel<<<(PP + QQ + 255) / 256, 256>>>(x, images, mu_s, sg_s, tptr);
    score_main_kernel<<<dim3(QTILES, NCHUNK), QPB>>>();
    finalize_kernel<<<(QQ + 255) / 256, 256>>>(x, mu_s, sg_s, tptr, out);
}

// round 7
// speedup vs baseline: 1.9404x; 1.5790x over previous
#include <cuda_runtime.h>
#include <cuda_bf16.h>
#include <math.h>
#include <cstdint>

// ---------------- problem constants ----------------
#define BB 4
#define CC 3
#define HH 32
#define WW 32
#define NIMG 32
#define PP (NIMG*HH*WW)      // 32768 dataset patches
#define QQ (BB*HH*WW)        // 4096 queries
#define KD 27                // raw feature dim
// split K': [qh*kh (27)] [qh*kl (27)] [ql*kh (27)] pad -> 96 = 6 chunks of k16
#define KCH 6

#define PSPLIT 9             // 32 qtiles * 9 = 288 blocks ~= 148*2 (one wave at occ 2)
#define NQT 32               // q tiles of 128 rows
#define NPG (PP/8)           // 4096 patch groups of 8

// ---------------- device scratch (no allocation allowed) -------------------
// K fragments: [pg][chunkpair 0..2][lane] uint4 = (b0_even,b1_even,b0_odd,b1_odd)
__device__ uint4  g_kfrag[NPG * 3 * 32];          // 6 MB
// Q fragments: [tile(16 rows)][chunk 0..5][lane] uint4 = (a0,a1,a2,a3)
__device__ uint4  g_qfrag[(QQ/16) * KCH * 32];    // 768 KB
__device__ float4 g_meta[PP];                     // c0,c1,c2,bias(log2 domain)
__device__ float  g_partial[QQ * PSPLIT * 8];     // m,sw,c0,c1,c2 per (q,split)

// ---------------- helpers ----------------------------------------------
__device__ __forceinline__ float ex2f(float x) {
    float r; asm("ex2.approx.f32 %0,%1;" : "=f"(r) : "f"(x)); return r;
}
__device__ __forceinline__ void split_bf16(float v, unsigned short& h, unsigned short& l) {
    __nv_bfloat16 hb = __float2bfloat16_rn(v);
    float rem = v - __bfloat162float(hb);
    __nv_bfloat16 lb = __float2bfloat16_rn(rem);
    h = __bfloat16_as_ushort(hb);
    l = __bfloat16_as_ushort(lb);
}
#define MMA_BF16(d0,d1,d2,d3,a0,a1,a2,a3,b0,b1) \
    asm volatile("mma.sync.aligned.m16n8k16.row.col.f32.bf16.bf16.f32 " \
                 "{%0,%1,%2,%3}, {%4,%5,%6,%7}, {%8,%9}, {%0,%1,%2,%3};" \
                 : "+f"(d0), "+f"(d1), "+f"(d2), "+f"(d3) \
                 : "r"(a0), "r"(a1), "r"(a2), "r"(a3), "r"(b0), "r"(b1))

// ---------------------------------------------------------------------------
// Prep: build fragment-major Q/K split-bf16 data + per-patch meta.
// log2-domain: q scaled by 2*mu/(2 sigma^2)*log2(e); bias = -mu^2/(2s^2)*log2e*||k||^2
// ---------------------------------------------------------------------------
__global__ void prep_kernel(const float* __restrict__ x,
                            const float* __restrict__ images,
                            const float* __restrict__ mu_sched,
                            const float* __restrict__ sigma_sched,
                            const int* __restrict__ tptr)
{
    const int t = *tptr;
    const float mu = mu_sched[t];
    const float sg = sigma_sched[t];
    const float LOG2E = 1.4426950408889634f;
    const float inv2s2 = 1.0f / (2.0f * sg * sg);
    const float a  = 2.0f * mu * inv2s2 * LOG2E;
    const float nb = -mu * mu * inv2s2 * LOG2E;

    int gid = blockIdx.x * blockDim.x + threadIdx.x;

    float f[KD];
    unsigned short hb[KD], lb[KD];
    unsigned short v[96];

    if (gid < PP) {
        // ---- dataset patch (zero pad) ----
        int p = gid;
        int n = p >> 10, i = (p >> 5) & 31, j = p & 31;
        float pn = 0.0f;
        #pragma unroll
        for (int c = 0; c < CC; c++)
            #pragma unroll
            for (int di = 0; di < 3; di++)
                #pragma unroll
                for (int dj = 0; dj < 3; dj++) {
                    int ii = i + di - 1, jj = j + dj - 1;
                    float vv = 0.0f;
                    if (ii >= 0 && ii < HH && jj >= 0 && jj < WW)
                        vv = images[(((n*CC + c) << 5) + ii) * WW + jj];
                    f[c*9 + di*3 + dj] = vv;
                    pn += vv * vv;
                }
        #pragma unroll
        for (int k = 0; k < KD; k++) split_bf16(f[k], hb[k], lb[k]);
        // B row: [kh(27)][kl(27)][kh(27)][pad]
        #pragma unroll
        for (int k = 0; k < 96; k++)
            v[k] = (k < 27) ? hb[k] : (k < 54) ? lb[k-27] : (k < 81) ? hb[k-54] : 0;

        int pg = p >> 3, nn = p & 7;
        #pragma unroll
        for (int cp = 0; cp < 3; cp++) {
            int c0 = 2*cp*16, c1 = (2*cp+1)*16;
            #pragma unroll
            for (int tt = 0; tt < 4; tt++) {
                uint4 val;
                val.x = (unsigned)v[c0 + 2*tt]     | ((unsigned)v[c0 + 2*tt + 1] << 16);
                val.y = (unsigned)v[c0 + 2*tt + 8] | ((unsigned)v[c0 + 2*tt + 9] << 16);
                val.z = (unsigned)v[c1 + 2*tt]     | ((unsigned)v[c1 + 2*tt + 1] << 16);
                val.w = (unsigned)v[c1 + 2*tt + 8] | ((unsigned)v[c1 + 2*tt + 9] << 16);
                g_kfrag[((pg*3 + cp) << 5) + nn*4 + tt] = val;
            }
        }
        g_meta[p] = make_float4(f[4], f[13], f[22], nb * pn);
    } else if (gid < PP + QQ) {
        // ---- query (wrap pad, scaled) ----
        int q = gid - PP;
        int b = q >> 10, h = (q >> 5) & 31, w0 = q & 31;
        #pragma unroll
        for (int c = 0; c < CC; c++)
            #pragma unroll
            for (int di = 0; di < 3; di++)
                #pragma unroll
                for (int dj = 0; dj < 3; dj++) {
                    int ii = (h + di - 1) & 31, jj = (w0 + dj - 1) & 31;
                    f[c*9 + di*3 + dj] = a * x[(((b*CC + c) << 5) + ii) * WW + jj];
                }
        #pragma unroll
        for (int k = 0; k < KD; k++) split_bf16(f[k], hb[k], lb[k]);
        // A row: [qh(27)][qh(27)][ql(27)][pad]
        #pragma unroll
        for (int k = 0; k < 96; k++)
            v[k] = (k < 27) ? hb[k] : (k < 54) ? hb[k-27] : (k < 81) ? lb[k-54] : 0;

        int tile = q >> 4, r = q & 15, rg = r & 7, rh = r >> 3;
        unsigned* qf = (unsigned*)g_qfrag;
        #pragma unroll
        for (int c = 0; c < KCH; c++) {
            #pragma unroll
            for (int tt = 0; tt < 4; tt++) {
                unsigned lo = (unsigned)v[c*16 + 2*tt]     | ((unsigned)v[c*16 + 2*tt + 1] << 16);
                unsigned hi = (unsigned)v[c*16 + 2*tt + 8] | ((unsigned)v[c*16 + 2*tt + 9] << 16);
                unsigned base4 = (((tile*KCH + c) << 5) + rg*4 + tt) << 2;
                qf[base4 + rh]     = lo;   // a0 (row g) or a1 (row g+8)
                qf[base4 + 2 + rh] = hi;   // a2 / a3
            }
        }
    }
}

// ---------------------------------------------------------------------------
// Main: mma.sync flash-attention. 288 blocks (32 qtiles x 9 psplits), 256 thr.
// Each warp: 16 q-rows, sweeps its split's patch groups (8 patches per step).
// ---------------------------------------------------------------------------
__device__ __forceinline__ void merge_state(float& m, float& sw, float& a,
                                            float& b, float& c, int off)
{
    float mo = __shfl_down_sync(0xffffffffu, m,  off, 4);
    float so = __shfl_down_sync(0xffffffffu, sw, off, 4);
    float ao = __shfl_down_sync(0xffffffffu, a,  off, 4);
    float bo = __shfl_down_sync(0xffffffffu, b,  off, 4);
    float co = __shfl_down_sync(0xffffffffu, c,  off, 4);
    float M  = fmaxf(m, mo);
    float f0 = ex2f(m - M), f1 = ex2f(mo - M);
    sw = sw*f0 + so*f1;
    a  = a*f0  + ao*f1;
    b  = b*f0  + bo*f1;
    c  = c*f0  + co*f1;
    m  = M;
}

__global__ void __launch_bounds__(256, 2)
score_main_kernel()
{
    const int bid  = blockIdx.x;
    const int qt   = bid & 31;
    const int sp   = bid >> 5;          // 0..8
    const int w    = threadIdx.x >> 5;
    const int lane = threadIdx.x & 31;
    const int g    = lane >> 2;         // q-row group (rows g, g+8)
    const int t    = lane & 3;          // column pair (cols 2t, 2t+1)

    // A fragments for this warp's 16 q-rows
    const int tile = qt * 8 + w;
    uint4 af[KCH];
    #pragma unroll
    for (int c = 0; c < KCH; c++)
        af[c] = g_qfrag[((tile*KCH + c) << 5) + lane];

    float m0 = -1e30f, sw0 = 0.f, c00 = 0.f, c01 = 0.f, c02 = 0.f;
    float m1 = -1e30f, sw1 = 0.f, c10 = 0.f, c11 = 0.f, c12 = 0.f;

    const int G0 = (NPG * sp) / PSPLIT;
    const int G1 = (NPG * (sp + 1)) / PSPLIT;

    #pragma unroll 2
    for (int pg = G0; pg < G1; pg++) {
        uint4 b01 = g_kfrag[((pg*3 + 0) << 5) + lane];
        uint4 b23 = g_kfrag[((pg*3 + 1) << 5) + lane];
        uint4 b45 = g_kfrag[((pg*3 + 2) << 5) + lane];
        float4 me0 = g_meta[(pg << 3) + 2*t];
        float4 me1 = g_meta[(pg << 3) + 2*t + 1];

        // D init = per-column bias
        float d0 = me0.w, d1 = me1.w, d2 = me0.w, d3 = me1.w;
        MMA_BF16(d0,d1,d2,d3, af[0].x,af[0].y,af[0].z,af[0].w, b01.x,b01.y);
        MMA_BF16(d0,d1,d2,d3, af[1].x,af[1].y,af[1].z,af[1].w, b01.z,b01.w);
        MMA_BF16(d0,d1,d2,d3, af[2].x,af[2].y,af[2].z,af[2].w, b23.x,b23.y);
        MMA_BF16(d0,d1,d2,d3, af[3].x,af[3].y,af[3].z,af[3].w, b23.z,b23.w);
        MMA_BF16(d0,d1,d2,d3, af[4].x,af[4].y,af[4].z,af[4].w, b45.x,b45.y);
        MMA_BF16(d0,d1,d2,d3, af[5].x,af[5].y,af[5].z,af[5].w, b45.z,b45.w);

        // row g: logits d0 (col 2t), d1 (col 2t+1)
        {
            float mx = fmaxf(d0, d1);
            if (mx > m0) {
                float cr = ex2f(m0 - mx);
                sw0 *= cr; c00 *= cr; c01 *= cr; c02 *= cr;
                m0 = mx;
            }
            float w0 = ex2f(d0 - m0), w1 = ex2f(d1 - m0);
            sw0 += w0 + w1;
            c00 += w0*me0.x + w1*me1.x;
            c01 += w0*me0.y + w1*me1.y;
            c02 += w0*me0.z + w1*me1.z;
        }
        // row g+8: logits d2, d3
        {
            float mx = fmaxf(d2, d3);
            if (mx > m1) {
                float cr = ex2f(m1 - mx);
                sw1 *= cr; c10 *= cr; c11 *= cr; c12 *= cr;
                m1 = mx;
            }
            float w0 = ex2f(d2 - m1), w1 = ex2f(d3 - m1);
            sw1 += w0 + w1;
            c10 += w0*me0.x + w1*me1.x;
            c11 += w0*me0.y + w1*me1.y;
            c12 += w0*me0.z + w1*me1.z;
        }
    }

    // reduce the 4 column-group lanes (t = 0..3) of each row
    #pragma unroll
    for (int off = 1; off <= 2; off <<= 1) {
        merge_state(m0, sw0, c00, c01, c02, off);
        merge_state(m1, sw1, c10, c11, c12, off);
    }

    if (t == 0) {
        int qrow0 = qt*128 + w*16 + g;
        float* o0 = g_partial + ((size_t)qrow0 * PSPLIT + sp) * 8;
        o0[0] = m0; o0[1] = sw0; o0[2] = c00; o0[3] = c01; o0[4] = c02;
        float* o1 = g_partial + ((size_t)(qrow0 + 8) * PSPLIT + sp) * 8;
        o1[0] = m1; o1[1] = sw1; o1[2] = c10; o1[3] = c11; o1[4] = c12;
    }
}

// ---------------------------------------------------------------------------
// Finalize: merge PSPLIT partials per query (log2 domain), form output.
// ---------------------------------------------------------------------------
__global__ void finalize_kernel(const float* __restrict__ x,
                                const float* __restrict__ mu_sched,
                                const float* __restrict__ sigma_sched,
                                const int* __restrict__ tptr,
                                float* __restrict__ out)
{
    int q = blockIdx.x * blockDim.x + threadIdx.x;
    if (q >= QQ) return;

    const int t = *tptr;
    const float mu = mu_sched[t];
    const float sg = sigma_sched[t];
    const float is2 = 1.0f / (sg * sg);

    const float* pr = g_partial + (size_t)q * PSPLIT * 8;

    float M = -1e30f;
    #pragma unroll
    for (int i = 0; i < PSPLIT; i++) M = fmaxf(M, pr[i*8]);

    float S = 0.f, c0 = 0.f, c1 = 0.f, c2 = 0.f;
    #pragma unroll
    for (int i = 0; i < PSPLIT; i++) {
        float cr = ex2f(pr[i*8] - M);
        S  += pr[i*8 + 1] * cr;
        c0 += pr[i*8 + 2] * cr;
        c1 += pr[i*8 + 3] * cr;
        c2 += pr[i*8 + 4] * cr;
    }
    float inv = 1.0f / S;

    int b = q >> 10;
    int pix = q & 1023;

    out[((b*CC + 0) << 10) + pix] = -(x[((b*CC + 0) << 10) + pix] - mu * c0 * inv) * is2;
    out[((b*CC + 1) << 10) + pix] = -(x[((b*CC + 1) << 10) + pix] - mu * c1 * inv) * is2;
    out[((b*CC + 2) << 10) + pix] = -(x[((b*CC + 2) << 10) + pix] - mu * c2 * inv) * is2;
}

// ---------------------------------------------------------------------------
extern "C" void kernel_launch(void* const* d_in, const int* in_sizes, int n_in,
                              void* d_out, int out_size)
{
    const float* x      = (const float*)d_in[0];
    const float* images = (const float*)d_in[1];
    const float* mu_s   = (const float*)d_in[2];
    const float* sg_s   = (const float*)d_in[3];
    const int*   tptr   = (const int*)d_in[4];
    float* out = (float*)d_out;

    prep_kernel<<<(PP + QQ + 255) / 256, 256>>>(x, images, mu_s, sg_s, tptr);
    score_main_kernel<<<NQT * PSPLIT, 256>>>();
    finalize_kernel<<<(QQ + 255) / 256, 256>>>(x, mu_s, sg_s, tptr, out);
}